// round 3
// baseline (speedup 1.0000x reference)
#include <cuda_runtime.h>
#include <cuda_bf16.h>
#include <math.h>

#define Bsz 2
#define S 2048
#define D 1024
#define H 16
#define KV 8
#define HD 64
#define WINDOW 512
#define M_TOT (Bsz * S)      // 4096

// Scratch (device globals; no allocation allowed)
__device__ float g_Q[M_TOT * (H * HD)];    // [b*s, 1024]
__device__ float g_K[M_TOT * (KV * HD)];   // [b*s, 512]
__device__ float g_V[M_TOT * (KV * HD)];   // [b*s, 512]
__device__ float g_O[M_TOT * (H * HD)];    // [b*s, 1024]

// ---------------------------------------------------------------------------
// Kernel 1: fused QKV GEMM + RoPE epilogue.
// C = X (4096x1024) @ [Wq | Wk | Wv] (1024 x 2048), 64x64 tiles.
// Column blocks: [0,1024) -> Q heads, [1024,1536) -> K heads, [1536,2048) -> V.
// ---------------------------------------------------------------------------
__global__ __launch_bounds__(256) void qkv_rope_kernel(
    const float* __restrict__ X,
    const float* __restrict__ Wq,
    const float* __restrict__ Wk,
    const float* __restrict__ Wv)
{
    __shared__ float As[16][64];
    __shared__ float Bs[16][64];
    __shared__ float Cs[64][65];

    const int nb = blockIdx.x;          // 0..31
    const int mb = blockIdx.y;          // 0..63
    const int gc0 = nb * 64;

    const float* Bp; int ldb, bcol0;
    if (gc0 < 1024)      { Bp = Wq; ldb = 1024; bcol0 = gc0; }
    else if (gc0 < 1536) { Bp = Wk; ldb = 512;  bcol0 = gc0 - 1024; }
    else                 { Bp = Wv; ldb = 512;  bcol0 = gc0 - 1536; }

    const int tid = threadIdx.x;
    const int tx = tid & 15;
    const int ty = tid >> 4;

    float acc[4][4];
#pragma unroll
    for (int i = 0; i < 4; i++)
#pragma unroll
        for (int j = 0; j < 4; j++) acc[i][j] = 0.f;

    const int arow = tid >> 2;          // 0..63
    const int ak   = (tid & 3) * 4;     // 0,4,8,12
    const int brow = tid >> 4;          // 0..15
    const int bcol = (tid & 15) * 4;    // 0..60

    const float* Ag = X + (size_t)(mb * 64 + arow) * 1024;

    for (int k0 = 0; k0 < 1024; k0 += 16) {
        float4 a4 = *(const float4*)(Ag + k0 + ak);
        As[ak + 0][arow] = a4.x;
        As[ak + 1][arow] = a4.y;
        As[ak + 2][arow] = a4.z;
        As[ak + 3][arow] = a4.w;
        float4 b4 = *(const float4*)(Bp + (size_t)(k0 + brow) * ldb + bcol0 + bcol);
        *(float4*)&Bs[brow][bcol] = b4;
        __syncthreads();
#pragma unroll
        for (int k = 0; k < 16; k++) {
            float a[4], b[4];
#pragma unroll
            for (int i = 0; i < 4; i++) a[i] = As[k][ty * 4 + i];
#pragma unroll
            for (int j = 0; j < 4; j++) b[j] = Bs[k][tx * 4 + j];
#pragma unroll
            for (int i = 0; i < 4; i++)
#pragma unroll
                for (int j = 0; j < 4; j++) acc[i][j] += a[i] * b[j];
        }
        __syncthreads();
    }

    // stage to shared for RoPE (needs paired columns d and d±32)
#pragma unroll
    for (int i = 0; i < 4; i++)
#pragma unroll
        for (int j = 0; j < 4; j++)
            Cs[ty * 4 + i][tx * 4 + j] = acc[i][j];
    __syncthreads();

    const bool isQ = (gc0 < 1024);
    const bool isK = (gc0 >= 1024) && (gc0 < 1536);

    for (int lin = tid; lin < 64 * 64; lin += 256) {
        const int r = lin >> 6;
        const int d = lin & 63;
        const int gm = mb * 64 + r;
        float val = Cs[r][d];
        if (isQ || isK) {
            const int t = gm & (S - 1);
            const int f = d & 31;
            const float invf = expf(-logf(10000.0f) * (float)f * (1.0f / 32.0f));
            const float ang = (float)t * invf;
            float cv, sv;
            sincosf(ang, &sv, &cv);
            const float rot = (d < 32) ? -Cs[r][d + 32] : Cs[r][d - 32];
            val = val * cv + rot * sv;
        }
        if (isQ)       g_Q[(size_t)gm * 1024 + gc0 + d] = val;
        else if (isK)  g_K[(size_t)gm * 512 + (gc0 - 1024) + d] = val;
        else           g_V[(size_t)gm * 512 + (gc0 - 1536) + d] = val;
    }
}

// ---------------------------------------------------------------------------
// Kernel 2: sliding-window causal attention, flash-style online softmax, fp32.
// grid = (S/64, B*H), 128 threads. Query tile 64, key tile 32.
// Thread (r = tid>>1, hc = tid&1): owns query row r; scores for 16 keys;
// output dims [hc*32, hc*32+32).
// ---------------------------------------------------------------------------
__global__ __launch_bounds__(128) void attn_kernel()
{
    __shared__ float Qs[64][65];
    __shared__ float KVs[32][65];
    __shared__ float Ps[64][65];

    const int bh = blockIdx.y;
    const int b = bh >> 4;
    const int h = bh & 15;
    const int kvh = h >> 1;          // n_rep = 2
    const int q0 = blockIdx.x * 64;

    const int tid = threadIdx.x;
    const int r = tid >> 1;
    const int hc = tid & 1;
    const int i = q0 + r;            // global query index

    const float* Qg = g_Q + ((size_t)(b * S + q0)) * 1024 + h * 64;
    for (int lin = tid; lin < 64 * 64; lin += 128) {
        int rr = lin >> 6, k = lin & 63;
        Qs[rr][k] = Qg[(size_t)rr * 1024 + k];
    }

    float o[32];
#pragma unroll
    for (int d = 0; d < 32; d++) o[d] = 0.f;
    float m = -1e30f, l = 0.f;

    const int t0 = max(0, q0 - WINDOW) >> 5;
    const int t1 = (q0 >> 5) + 1;

    const float* Kg = g_K + ((size_t)b * S) * 512 + kvh * 64;
    const float* Vg = g_V + ((size_t)b * S) * 512 + kvh * 64;

    __syncthreads();

    for (int t = t0; t <= t1; t++) {
        const int j0 = t << 5;

        // load K tile (32 keys x 64 dims)
        for (int lin = tid; lin < 32 * 64; lin += 128) {
            int c = lin >> 6, k = lin & 63;
            KVs[c][k] = Kg[(size_t)(j0 + c) * 512 + k];
        }
        __syncthreads();

        float s[16];
#pragma unroll
        for (int c = 0; c < 16; c++) s[c] = 0.f;
        for (int k = 0; k < 64; k++) {
            const float qv = Qs[r][k];
#pragma unroll
            for (int c = 0; c < 16; c++) s[c] += qv * KVs[hc * 16 + c][k];
        }

        float tmax = -1e30f;
#pragma unroll
        for (int c = 0; c < 16; c++) {
            const int j = j0 + hc * 16 + c;
            const bool ok = (j <= i) && (j >= i - WINDOW);
            s[c] = ok ? s[c] * 0.125f : -1e30f;
            tmax = fmaxf(tmax, s[c]);
        }
        tmax = fmaxf(tmax, __shfl_xor_sync(0xffffffffu, tmax, 1));
        const float mnew = fmaxf(m, tmax);
        const float scale = __expf(m - mnew);

        float psum = 0.f;
#pragma unroll
        for (int c = 0; c < 16; c++) {
            const float p = (s[c] > -1e29f) ? __expf(s[c] - mnew) : 0.f;
            Ps[r][hc * 16 + c] = p;
            psum += p;
        }
        l = l * scale + psum;
        m = mnew;
#pragma unroll
        for (int d = 0; d < 32; d++) o[d] *= scale;

        __syncthreads();   // scores done reading K; Ps written

        // load V tile over K
        for (int lin = tid; lin < 32 * 64; lin += 128) {
            int c = lin >> 6, k = lin & 63;
            KVs[c][k] = Vg[(size_t)(j0 + c) * 512 + k];
        }
        __syncthreads();

#pragma unroll 4
        for (int c = 0; c < 32; c++) {
            const float p = Ps[r][c];
#pragma unroll
            for (int d = 0; d < 32; d++) o[d] += p * KVs[c][hc * 32 + d];
        }
        __syncthreads();   // before next tile overwrites KVs / Ps
    }

    float ltot = l + __shfl_xor_sync(0xffffffffu, l, 1);
    const float inv = 1.f / ltot;
    float* Og = g_O + ((size_t)(b * S + i)) * 1024 + h * 64 + hc * 32;
#pragma unroll
    for (int d = 0; d < 32; d++) Og[d] = o[d] * inv;
}

// ---------------------------------------------------------------------------
// Kernel 3: output projection: out = g_O (4096x1024) @ Wo (1024x1024)
// ---------------------------------------------------------------------------
__global__ __launch_bounds__(256) void outproj_kernel(
    const float* __restrict__ Wo, float* __restrict__ out)
{
    __shared__ float As[16][64];
    __shared__ float Bs[16][64];

    const int nb = blockIdx.x;   // 0..15
    const int mb = blockIdx.y;   // 0..63
    const int gc0 = nb * 64;

    const int tid = threadIdx.x;
    const int tx = tid & 15;
    const int ty = tid >> 4;

    float acc[4][4];
#pragma unroll
    for (int i = 0; i < 4; i++)
#pragma unroll
        for (int j = 0; j < 4; j++) acc[i][j] = 0.f;

    const int arow = tid >> 2;
    const int ak   = (tid & 3) * 4;
    const int brow = tid >> 4;
    const int bcol = (tid & 15) * 4;

    const float* Ag = g_O + (size_t)(mb * 64 + arow) * 1024;

    for (int k0 = 0; k0 < 1024; k0 += 16) {
        float4 a4 = *(const float4*)(Ag + k0 + ak);
        As[ak + 0][arow] = a4.x;
        As[ak + 1][arow] = a4.y;
        As[ak + 2][arow] = a4.z;
        As[ak + 3][arow] = a4.w;
        float4 b4 = *(const float4*)(Wo + (size_t)(k0 + brow) * 1024 + gc0 + bcol);
        *(float4*)&Bs[brow][bcol] = b4;
        __syncthreads();
#pragma unroll
        for (int k = 0; k < 16; k++) {
            float a[4], bb[4];
#pragma unroll
            for (int i = 0; i < 4; i++) a[i] = As[k][ty * 4 + i];
#pragma unroll
            for (int j = 0; j < 4; j++) bb[j] = Bs[k][tx * 4 + j];
#pragma unroll
            for (int i = 0; i < 4; i++)
#pragma unroll
                for (int j = 0; j < 4; j++) acc[i][j] += a[i] * bb[j];
        }
        __syncthreads();
    }

#pragma unroll
    for (int i = 0; i < 4; i++) {
        const int gm = mb * 64 + ty * 4 + i;
#pragma unroll
        for (int j = 0; j < 4; j++) {
            out[(size_t)gm * 1024 + gc0 + tx * 4 + j] = acc[i][j];
        }
    }
}

extern "C" void kernel_launch(void* const* d_in, const int* in_sizes, int n_in,
                              void* d_out, int out_size)
{
    const float* X  = (const float*)d_in[0];
    const float* Wq = (const float*)d_in[1];
    const float* Wk = (const float*)d_in[2];
    const float* Wv = (const float*)d_in[3];
    const float* Wo = (const float*)d_in[4];
    float* out = (float*)d_out;

    qkv_rope_kernel<<<dim3(32, 64), 256>>>(X, Wq, Wk, Wv);
    attn_kernel<<<dim3(S / 64, Bsz * H), 128>>>();
    outproj_kernel<<<dim3(16, 64), 256>>>(Wo, out);
}